// round 8
// baseline (speedup 1.0000x reference)
#include <cuda_runtime.h>
#include <cuda_fp16.h>
#include <cstdint>

#define NN 20000
#define EE 640000
#define FF 32
#define HH 4
#define CC 64
#define SS 6
#define BB 16
#define DD 64
#define HC 256   // H*C
#define NP 6     // buffer sets (one per timestep; streams stay at 3)
#define NST 3    // streams (proven memory-safe count)

// ---------------- device scratch ----------------
__device__ int    g_counts[NN];
__device__ int    g_rowptr[NN + 1];
__device__ int    g_wpos[NN];
__device__ int    g_col[EE];
__device__ int    g_batchcnt[BB];
__device__ __half g_h1[NP][(size_t)NN * HC];
__device__ float4 g_ssrc1[NP][NN];
__device__ float4 g_sdst1[NP][NN];
__device__ __half g_h2[NP][(size_t)NN * CC];
__device__ float  g_ssrc2[NP][NN];
__device__ float  g_sdst2[NP][NN];
__device__ float  g_pooled[BB * SS * DD];
__device__ float  g_sx[96 * 64];
__device__ float  g_qkv[96 * 192];

__device__ __forceinline__ float lrelu(float x) { return x > 0.f ? x : 0.2f * x; }
__device__ __forceinline__ float warpSum(float v) {
#pragma unroll
  for (int o = 16; o; o >>= 1) v += __shfl_xor_sync(0xffffffffu, v, o);
  return v;
}

// ---------------- init + CSR build ----------------
__global__ void k_init() {
  int i = blockIdx.x * blockDim.x + threadIdx.x;
  if (i < NN) g_counts[i] = 0;
  if (i < BB * SS * DD) g_pooled[i] = 0.f;
  if (i < BB) g_batchcnt[i] = 0;
}

__global__ void k_hist(const int* __restrict__ ei, const int* __restrict__ batch) {
  int i = blockIdx.x * blockDim.x + threadIdx.x;
  if (i < EE) atomicAdd(&g_counts[ei[EE + i]], 1);
  if (i < NN) atomicAdd(&g_batchcnt[batch[i]], 1);
}

__global__ void k_scan() {
  __shared__ int wsum[32];
  __shared__ int carry;
  int tid = threadIdx.x, lane = tid & 31, wid = tid >> 5;
  if (tid == 0) carry = 0;
  __syncthreads();
  for (int base = 0; base < NN; base += 1024) {
    int i = base + tid;
    int v = (i < NN) ? g_counts[i] : 0;
    int incl = v;
#pragma unroll
    for (int o = 1; o < 32; o <<= 1) { int u = __shfl_up_sync(0xffffffffu, incl, o); if (lane >= o) incl += u; }
    if (lane == 31) wsum[wid] = incl;
    __syncthreads();
    if (wid == 0) {
      int ws = wsum[lane];
      int wi = ws;
#pragma unroll
      for (int o = 1; o < 32; o <<= 1) { int u = __shfl_up_sync(0xffffffffu, wi, o); if (lane >= o) wi += u; }
      wsum[lane] = wi - ws;
    }
    __syncthreads();
    int excl = incl - v + wsum[wid] + carry;
    if (i < NN) { g_rowptr[i] = excl; g_wpos[i] = excl; }
    __syncthreads();
    if (tid == 1023) carry = excl + v;
    __syncthreads();
  }
  if (threadIdx.x == 0) g_rowptr[NN] = carry;
}

__global__ void k_scatter(const int* __restrict__ ei) {
  int i = blockIdx.x * blockDim.x + threadIdx.x;
  if (i >= EE) return;
  int d = ei[EE + i];
  int p = atomicAdd(&g_wpos[d], 1);
  g_col[p] = ei[i];
}

// ---------------- GEMM1: h1 = x @ W1 (fp16 out) ; fused attn scores ----------------
__global__ __launch_bounds__(256) void k_gemm1(const float* __restrict__ x,
                                               const float* __restrict__ W1,
                                               const float* __restrict__ as1,
                                               const float* __restrict__ ad1, int p) {
  __shared__ float Ws[FF * HC];
  __shared__ float Xs[64][33];
  int tid = threadIdx.x;
  for (int i = tid; i < FF * HC / 4; i += 256) ((float4*)Ws)[i] = ((const float4*)W1)[i];
  int m0 = blockIdx.x * 64;
  for (int i = tid; i < 512; i += 256) {
    int r = i >> 3, c4 = i & 7;
    float4 v = make_float4(0.f, 0.f, 0.f, 0.f);
    if (m0 + r < NN) v = ((const float4*)(x + (size_t)(m0 + r) * FF))[c4];
    Xs[r][c4 * 4 + 0] = v.x; Xs[r][c4 * 4 + 1] = v.y;
    Xs[r][c4 * 4 + 2] = v.z; Xs[r][c4 * 4 + 3] = v.w;
  }
  __syncthreads();
  int tx = tid & 31, ty = tid >> 5;
  float acc[8][8] = {};
#pragma unroll
  for (int k = 0; k < FF; k++) {
    float a[8];
#pragma unroll
    for (int i = 0; i < 8; i++) a[i] = Xs[ty * 8 + i][k];
    float4 b0 = *(const float4*)(Ws + k * HC + tx * 8);
    float4 b1v = *(const float4*)(Ws + k * HC + tx * 8 + 4);
    float b[8] = {b0.x, b0.y, b0.z, b0.w, b1v.x, b1v.y, b1v.z, b1v.w};
#pragma unroll
    for (int i = 0; i < 8; i++)
#pragma unroll
      for (int j = 0; j < 8; j++) acc[i][j] += a[i] * b[j];
  }
  float asr[8], adr[8];
#pragma unroll
  for (int j = 0; j < 8; j++) { asr[j] = __ldg(as1 + tx * 8 + j); adr[j] = __ldg(ad1 + tx * 8 + j); }
#pragma unroll
  for (int i = 0; i < 8; i++) {
    int row = m0 + ty * 8 + i;
    float ps = 0.f, pd = 0.f;
#pragma unroll
    for (int j = 0; j < 8; j++) { ps += acc[i][j] * asr[j]; pd += acc[i][j] * adr[j]; }
#pragma unroll
    for (int o = 4; o; o >>= 1) {
      ps += __shfl_down_sync(0xffffffffu, ps, o, 8);
      pd += __shfl_down_sync(0xffffffffu, pd, o, 8);
    }
    if (row < NN) {
      if ((tx & 7) == 0) {
        ((float*)&g_ssrc1[p][row])[tx >> 3] = ps;
        ((float*)&g_sdst1[p][row])[tx >> 3] = pd;
      }
      uint4 u;
      ((__half2*)&u)[0] = __floats2half2_rn(acc[i][0], acc[i][1]);
      ((__half2*)&u)[1] = __floats2half2_rn(acc[i][2], acc[i][3]);
      ((__half2*)&u)[2] = __floats2half2_rn(acc[i][4], acc[i][5]);
      ((__half2*)&u)[3] = __floats2half2_rn(acc[i][6], acc[i][7]);
      ((uint4*)(g_h1[p] + (size_t)row * HC))[tx] = u;
    }
  }
}

// ---------------- GAT1 fused with GEMM2 + scores2 ----------------
// warp per dst node: softmax-aggregate (out1 row in regs) -> relu+bias ->
// stage to smem -> matvec with fp16 W2 in smem -> h2 + scores2, no out1 buffer.
__global__ __launch_bounds__(256) void k_gat1f(const float* __restrict__ b1,
                                               const float* __restrict__ W2,
                                               const float* __restrict__ as2,
                                               const float* __restrict__ ad2, int p) {
  __shared__ __half2 W2s[HC * 32];      // 32 KB: W2s[k*32+l] = (W2[k][2l], W2[k][2l+1])
  __shared__ int     sIdx[8][32];
  __shared__ float4  sE[8][32];
  __shared__ float   sO[8][HC];         // 8 KB: staged out1 rows
  int tid = threadIdx.x;
  // cooperative fp32->fp16 W2 staging
  for (int i = tid; i < HC * 32; i += 256) {
    float2 f = ((const float2*)W2)[i];
    W2s[i] = __floats2half2_rn(f.x, f.y);
  }
  __syncthreads();

  int wslot = tid >> 5;
  int gw = (blockIdx.x * blockDim.x + tid) >> 5;
  if (gw >= NN) return;
  int lane = tid & 31;
  int base = g_rowptr[gw];
  int deg = g_rowptr[gw + 1] - base;     // +1 virtual self loop at index deg
  float4 sd = g_sdst1[p][gw];
  int head = lane >> 3;
  const __half* h1p = g_h1[p];
  float acc[8] = {0, 0, 0, 0, 0, 0, 0, 0};
  float s0 = 0, s1 = 0, s2 = 0, s3 = 0;

  for (int c0 = 0; c0 <= deg; c0 += 32) {
    int i = c0 + lane;
    float4 e4 = {0, 0, 0, 0};
    int s = gw;
    if (i <= deg) {
      s = (i < deg) ? g_col[base + i] : gw;
      float4 ss = g_ssrc1[p][s];
      e4.x = __expf(lrelu(ss.x + sd.x));
      e4.y = __expf(lrelu(ss.y + sd.y));
      e4.z = __expf(lrelu(ss.z + sd.z));
      e4.w = __expf(lrelu(ss.w + sd.w));
      s0 += e4.x; s1 += e4.y; s2 += e4.z; s3 += e4.w;
    }
    sIdx[wslot][lane] = s;
    sE[wslot][lane] = e4;
    __syncwarp();
    int cnt = min(32, deg + 1 - c0);
#pragma unroll 4
    for (int j = 0; j < cnt; j++) {
      int sj = sIdx[wslot][j];
      float w = ((const float*)&sE[wslot][j])[head];
      uint4 raw = ((const uint4*)(h1p + (size_t)sj * HC))[lane];
      const __half2* ph = (const __half2*)&raw;
      float2 f0 = __half22float2(ph[0]);
      float2 f1 = __half22float2(ph[1]);
      float2 f2 = __half22float2(ph[2]);
      float2 f3 = __half22float2(ph[3]);
      acc[0] += w * f0.x; acc[1] += w * f0.y;
      acc[2] += w * f1.x; acc[3] += w * f1.y;
      acc[4] += w * f2.x; acc[5] += w * f2.y;
      acc[6] += w * f3.x; acc[7] += w * f3.y;
    }
    __syncwarp();
  }
  s0 = warpSum(s0); s1 = warpSum(s1); s2 = warpSum(s2); s3 = warpSum(s3);
  float sums[4] = {s0, s1, s2, s3};
  float inv = 1.f / sums[head];
  float4 bb0 = *(const float4*)(b1 + lane * 8);
  float4 bb1 = *(const float4*)(b1 + lane * 8 + 4);
  float bbs[8] = {bb0.x, bb0.y, bb0.z, bb0.w, bb1.x, bb1.y, bb1.z, bb1.w};
  float* so = &sO[wslot][0];
#pragma unroll
  for (int j = 0; j < 8; j++) so[lane * 8 + j] = fmaxf(acc[j] * inv + bbs[j], 0.f);
  __syncwarp();

  // matvec: h2[gw][2*lane], h2[gw][2*lane+1] = out1row @ W2 columns
  float a0 = 0.f, a1 = 0.f;
#pragma unroll 4
  for (int k = 0; k < HC; k += 4) {
    float4 h4 = *(const float4*)(so + k);  // broadcast
    float2 w0 = __half22float2(W2s[(k + 0) * 32 + lane]);
    float2 w1 = __half22float2(W2s[(k + 1) * 32 + lane]);
    float2 w2 = __half22float2(W2s[(k + 2) * 32 + lane]);
    float2 w3 = __half22float2(W2s[(k + 3) * 32 + lane]);
    a0 += h4.x * w0.x + h4.y * w1.x + h4.z * w2.x + h4.w * w3.x;
    a1 += h4.x * w0.y + h4.y * w1.y + h4.z * w2.y + h4.w * w3.y;
  }
  // scores2
  float ps = a0 * __ldg(as2 + 2 * lane) + a1 * __ldg(as2 + 2 * lane + 1);
  float pd = a0 * __ldg(ad2 + 2 * lane) + a1 * __ldg(ad2 + 2 * lane + 1);
  ps = warpSum(ps);
  pd = warpSum(pd);
  if (lane == 0) { g_ssrc2[p][gw] = ps; g_sdst2[p][gw] = pd; }
  ((__half2*)g_h2[p])[gw * 32 + lane] = __floats2half2_rn(a0, a1);
}

// ---------------- GAT2: single-pass aggregate + mean-pool scatter ----------------
__global__ __launch_bounds__(256) void k_gat2(const float* __restrict__ b2,
                                              const int* __restrict__ batch, int t, int p) {
  __shared__ int   sIdx[8][32];
  __shared__ float sEs[8][32];
  int wslot = threadIdx.x >> 5;
  int gw = (blockIdx.x * blockDim.x + threadIdx.x) >> 5;
  if (gw >= NN) return;
  int lane = threadIdx.x & 31;
  int base = g_rowptr[gw];
  int deg = g_rowptr[gw + 1] - base;
  float sd = g_sdst2[p][gw];
  const __half* h2p = g_h2[p];
  const float* ss2 = g_ssrc2[p];
  float2 acc = {0, 0};
  float sum = 0.f;

  for (int c0 = 0; c0 <= deg; c0 += 32) {
    int i = c0 + lane;
    float e = 0.f;
    int s = gw;
    if (i <= deg) {
      s = (i < deg) ? g_col[base + i] : gw;
      e = __expf(lrelu(ss2[s] + sd));
      sum += e;
    }
    sIdx[wslot][lane] = s;
    sEs[wslot][lane] = e;
    __syncwarp();
    int cnt = min(32, deg + 1 - c0);
#pragma unroll 4
    for (int j = 0; j < cnt; j++) {
      int sj = sIdx[wslot][j];
      float ej = sEs[wslot][j];
      float2 v = __half22float2(((const __half2*)(h2p + (size_t)sj * 64))[lane]);
      acc.x += ej * v.x;
      acc.y += ej * v.y;
    }
    __syncwarp();
  }
  sum = warpSum(sum);
  float inv = 1.f / sum;
  int b = batch[gw];
  float v0 = acc.x * inv + b2[lane * 2];
  float v1 = acc.y * inv + b2[lane * 2 + 1];
  atomicAdd(&g_pooled[b * (SS * DD) + t * DD + lane * 2], v0);
  atomicAdd(&g_pooled[b * (SS * DD) + t * DD + lane * 2 + 1], v1);
}

// ---------------- final A: mean-pool normalize + qkv projection (96 blocks) ----------------
__global__ __launch_bounds__(192) void k_final_a(const float* __restrict__ ipw,
                                                 const float* __restrict__ ipb) {
  __shared__ float xr[64];
  int r = blockIdx.x;
  int tid = threadIdx.x;
  if (tid < 64) {
    int c = g_batchcnt[r / 6];
    float inv = 1.f / (c > 0 ? (float)c : 1.f);
    float v = g_pooled[r * 64 + tid] * inv;
    xr[tid] = v;
    g_sx[r * 64 + tid] = v;
  }
  __syncthreads();
  float acc = ipb[tid];
  const float* wr = &ipw[tid * 64];
#pragma unroll 8
  for (int c = 0; c < 64; c++) acc += xr[c] * wr[c];
  g_qkv[r * 192 + tid] = acc;
}

// ---------------- final B: attention + out_proj + LN + temporal mean + proj (16 blocks) ----------------
__global__ __launch_bounds__(128) void k_final_b(const float* __restrict__ opw, const float* __restrict__ opb,
                                                 const float* __restrict__ lng, const float* __restrict__ lnb,
                                                 const float* __restrict__ pw,  const float* __restrict__ pb,
                                                 float* __restrict__ out) {
  __shared__ float q[6 * 192];
  __shared__ float att[6 * 64];
  __shared__ float ym[6 * 64];
  __shared__ float zacc[64];
  int b = blockIdx.x;
  int tid = threadIdx.x;
  for (int i = tid; i < 6 * 192; i += 128) q[i] = g_qkv[b * 6 * 192 + i];
  if (tid < 64) zacc[tid] = 0.f;
  __syncthreads();
  if (tid < 24) {
    int s1 = tid >> 2, h = tid & 3;
    float sc[6];
    float mx = -1e30f;
    const float* qr = &q[s1 * 192 + h * 16];
    for (int s2 = 0; s2 < 6; s2++) {
      const float* kr = &q[s2 * 192 + 64 + h * 16];
      float d = 0.f;
#pragma unroll
      for (int u = 0; u < 16; u++) d += qr[u] * kr[u];
      sc[s2] = d * 0.25f;
      mx = fmaxf(mx, sc[s2]);
    }
    float ssum = 0.f;
    for (int s2 = 0; s2 < 6; s2++) { sc[s2] = __expf(sc[s2] - mx); ssum += sc[s2]; }
    float invs = 1.f / ssum;
    float o[16];
#pragma unroll
    for (int u = 0; u < 16; u++) o[u] = 0.f;
    for (int s2 = 0; s2 < 6; s2++) {
      float w = sc[s2] * invs;
      const float* vr = &q[s2 * 192 + 128 + h * 16];
#pragma unroll
      for (int u = 0; u < 16; u++) o[u] += w * vr[u];
    }
    for (int u = 0; u < 16; u++) att[s1 * 64 + h * 16 + u] = o[u];
  }
  __syncthreads();
  for (int i = tid; i < 6 * 64; i += 128) {
    int r = i >> 6, c = i & 63;
    float acc = opb[c];
    const float* ar = &att[r * 64];
    const float* wr = &opw[c * 64];
#pragma unroll 8
    for (int k = 0; k < 64; k++) acc += ar[k] * wr[k];
    ym[i] = acc + g_sx[(b * 6 + r) * 64 + c];
  }
  __syncthreads();
  int wid = tid >> 5, lane = tid & 31;
  for (int row = wid; row < 6; row += 4) {
    float y0 = ym[row * 64 + lane];
    float y1 = ym[row * 64 + 32 + lane];
    float s = warpSum(y0 + y1);
    float mu = s * (1.f / 64.f);
    float d0 = y0 - mu, d1 = y1 - mu;
    float vs = warpSum(d0 * d0 + d1 * d1);
    float var = vs * (1.f / 64.f);
    float r = rsqrtf(var + 1e-5f);
    float z0 = d0 * r * lng[lane] + lnb[lane];
    float z1 = d1 * r * lng[lane + 32] + lnb[lane + 32];
    atomicAdd(&zacc[lane], z0 * (1.f / 6.f));
    atomicAdd(&zacc[lane + 32], z1 * (1.f / 6.f));
  }
  __syncthreads();
  if (tid < 64) {
    float acc = pb[tid];
    const float* wr = &pw[tid * 64];
#pragma unroll 8
    for (int k = 0; k < 64; k++) acc += zacc[k] * wr[k];
    out[b * 64 + tid] = acc;
  }
}

// ---------------- launch ----------------
extern "C" void kernel_launch(void* const* d_in, const int* in_sizes, int n_in,
                              void* d_out, int out_size) {
  const float* x_seq = (const float*)d_in[0];
  const int*   ei    = (const int*)d_in[1];
  const int*   batch = (const int*)d_in[2];
  const float* W1    = (const float*)d_in[3];
  const float* as1   = (const float*)d_in[4];
  const float* ad1   = (const float*)d_in[5];
  const float* b1    = (const float*)d_in[6];
  const float* W2    = (const float*)d_in[7];
  const float* as2   = (const float*)d_in[8];
  const float* ad2   = (const float*)d_in[9];
  const float* b2    = (const float*)d_in[10];
  const float* ipw   = (const float*)d_in[11];
  const float* ipb   = (const float*)d_in[12];
  const float* opw   = (const float*)d_in[13];
  const float* opb   = (const float*)d_in[14];
  const float* lng   = (const float*)d_in[15];
  const float* lnb   = (const float*)d_in[16];
  const float* pw    = (const float*)d_in[17];
  const float* pb    = (const float*)d_in[18];
  float* out = (float*)d_out;

  // One-time handles (same count as R6, which measured zero allocator delta).
  static bool inited = false;
  static cudaStream_t st[NST];
  static cudaEvent_t ev_root, ev_csr;
  static cudaEvent_t ev_done[NST];
  if (!inited) {
    for (int i = 0; i < NST; i++) {
      cudaStreamCreateWithFlags(&st[i], cudaStreamNonBlocking);
      cudaEventCreateWithFlags(&ev_done[i], cudaEventDisableTiming);
    }
    cudaEventCreateWithFlags(&ev_root, cudaEventDisableTiming);
    cudaEventCreateWithFlags(&ev_csr, cudaEventDisableTiming);
    inited = true;
  }

  // Fork worker streams off the capture stream.
  cudaEventRecord(ev_root, 0);
  for (int i = 0; i < NST; i++) cudaStreamWaitEvent(st[i], ev_root, 0);

  // CSR build on the legacy stream — overlaps with the gemm1s on workers.
  k_init<<<(NN + 255) / 256, 256>>>();
  k_hist<<<(EE + 255) / 256, 256>>>(ei, batch);
  k_scan<<<1, 1024>>>();
  k_scatter<<<(EE + 255) / 256, 256>>>(ei);
  cudaEventRecord(ev_csr, 0);

  // Both gemm1s per stream up front (independent of CSR), then the gat chains.
  for (int i = 0; i < NST; i++) {
    cudaStream_t s = st[i];
    k_gemm1<<<(NN + 63) / 64, 256, 0, s>>>(x_seq + (size_t)i * NN * FF, W1, as1, ad1, i);
    k_gemm1<<<(NN + 63) / 64, 256, 0, s>>>(x_seq + (size_t)(i + 3) * NN * FF, W1, as1, ad1, i + 3);
    cudaStreamWaitEvent(s, ev_csr, 0);
    k_gat1f<<<(NN * 32 + 255) / 256, 256, 0, s>>>(b1, W2, as2, ad2, i);
    k_gat2<<<(NN * 32 + 255) / 256, 256, 0, s>>>(b2, batch, i, i);
    k_gat1f<<<(NN * 32 + 255) / 256, 256, 0, s>>>(b1, W2, as2, ad2, i + 3);
    k_gat2<<<(NN * 32 + 255) / 256, 256, 0, s>>>(b2, batch, i + 3, i + 3);
  }
  for (int i = 0; i < NST; i++) {
    cudaEventRecord(ev_done[i], st[i]);
    cudaStreamWaitEvent(0, ev_done[i], 0);
  }

  k_final_a<<<96, 192>>>(ipw, ipb);
  k_final_b<<<16, 128>>>(opw, opb, lng, lnb, pw, pb, out);
}

// round 9
// speedup vs baseline: 1.1282x; 1.1282x over previous
#include <cuda_runtime.h>
#include <cuda_fp16.h>
#include <cstdint>

#define NN 20000
#define EE 640000
#define FF 32
#define HH 4
#define CC 64
#define SS 6
#define BB 16
#define DD 64
#define HC 256   // H*C
#define NP 6     // buffer sets (one per timestep)
#define NST 3    // worker streams (legacy stream is the 4th chain carrier)

// ---------------- device scratch ----------------
__device__ int    g_counts[NN];
__device__ int    g_rowptr[NN + 1];
__device__ int    g_wpos[NN];
__device__ int    g_col[EE];
__device__ int    g_batchcnt[BB];
__device__ __half g_h1[NP][(size_t)NN * HC];
__device__ __half g_out1[NP][(size_t)NN * HC];
__device__ float4 g_ssrc1[NP][NN];
__device__ float4 g_sdst1[NP][NN];
__device__ __half g_h2[NP][(size_t)NN * CC];
__device__ float  g_ssrc2[NP][NN];
__device__ float  g_sdst2[NP][NN];
__device__ float  g_pooled[BB * SS * DD];
__device__ float  g_sx[96 * 64];
__device__ float  g_qkv[96 * 192];

__device__ __forceinline__ float lrelu(float x) { return x > 0.f ? x : 0.2f * x; }
__device__ __forceinline__ float warpSum(float v) {
#pragma unroll
  for (int o = 16; o; o >>= 1) v += __shfl_xor_sync(0xffffffffu, v, o);
  return v;
}

// ---------------- init + CSR build ----------------
__global__ void k_init() {
  int i = blockIdx.x * blockDim.x + threadIdx.x;
  if (i < NN) g_counts[i] = 0;
  if (i < BB * SS * DD) g_pooled[i] = 0.f;
  if (i < BB) g_batchcnt[i] = 0;
}

__global__ void k_hist(const int* __restrict__ ei, const int* __restrict__ batch) {
  int i = blockIdx.x * blockDim.x + threadIdx.x;
  if (i < EE) atomicAdd(&g_counts[ei[EE + i]], 1);
  if (i < NN) atomicAdd(&g_batchcnt[batch[i]], 1);
}

__global__ void k_scan() {
  __shared__ int wsum[32];
  __shared__ int carry;
  int tid = threadIdx.x, lane = tid & 31, wid = tid >> 5;
  if (tid == 0) carry = 0;
  __syncthreads();
  for (int base = 0; base < NN; base += 1024) {
    int i = base + tid;
    int v = (i < NN) ? g_counts[i] : 0;
    int incl = v;
#pragma unroll
    for (int o = 1; o < 32; o <<= 1) { int u = __shfl_up_sync(0xffffffffu, incl, o); if (lane >= o) incl += u; }
    if (lane == 31) wsum[wid] = incl;
    __syncthreads();
    if (wid == 0) {
      int ws = wsum[lane];
      int wi = ws;
#pragma unroll
      for (int o = 1; o < 32; o <<= 1) { int u = __shfl_up_sync(0xffffffffu, wi, o); if (lane >= o) wi += u; }
      wsum[lane] = wi - ws;
    }
    __syncthreads();
    int excl = incl - v + wsum[wid] + carry;
    if (i < NN) { g_rowptr[i] = excl; g_wpos[i] = excl; }
    __syncthreads();
    if (tid == 1023) carry = excl + v;
    __syncthreads();
  }
  if (threadIdx.x == 0) g_rowptr[NN] = carry;
}

__global__ void k_scatter(const int* __restrict__ ei) {
  int i = blockIdx.x * blockDim.x + threadIdx.x;
  if (i >= EE) return;
  int d = ei[EE + i];
  int p = atomicAdd(&g_wpos[d], 1);
  g_col[p] = ei[i];
}

// ---------------- GEMM1: h1 = x @ W1 (fp16 out) ; fused attn scores ----------------
__global__ __launch_bounds__(256) void k_gemm1(const float* __restrict__ x,
                                               const float* __restrict__ W1,
                                               const float* __restrict__ as1,
                                               const float* __restrict__ ad1, int p) {
  __shared__ float Ws[FF * HC];
  __shared__ float Xs[64][33];
  int tid = threadIdx.x;
  for (int i = tid; i < FF * HC / 4; i += 256) ((float4*)Ws)[i] = ((const float4*)W1)[i];
  int m0 = blockIdx.x * 64;
  for (int i = tid; i < 512; i += 256) {
    int r = i >> 3, c4 = i & 7;
    float4 v = make_float4(0.f, 0.f, 0.f, 0.f);
    if (m0 + r < NN) v = ((const float4*)(x + (size_t)(m0 + r) * FF))[c4];
    Xs[r][c4 * 4 + 0] = v.x; Xs[r][c4 * 4 + 1] = v.y;
    Xs[r][c4 * 4 + 2] = v.z; Xs[r][c4 * 4 + 3] = v.w;
  }
  __syncthreads();
  int tx = tid & 31, ty = tid >> 5;
  float acc[8][8] = {};
#pragma unroll
  for (int k = 0; k < FF; k++) {
    float a[8];
#pragma unroll
    for (int i = 0; i < 8; i++) a[i] = Xs[ty * 8 + i][k];
    float4 b0 = *(const float4*)(Ws + k * HC + tx * 8);
    float4 b1v = *(const float4*)(Ws + k * HC + tx * 8 + 4);
    float b[8] = {b0.x, b0.y, b0.z, b0.w, b1v.x, b1v.y, b1v.z, b1v.w};
#pragma unroll
    for (int i = 0; i < 8; i++)
#pragma unroll
      for (int j = 0; j < 8; j++) acc[i][j] += a[i] * b[j];
  }
  float asr[8], adr[8];
#pragma unroll
  for (int j = 0; j < 8; j++) { asr[j] = __ldg(as1 + tx * 8 + j); adr[j] = __ldg(ad1 + tx * 8 + j); }
#pragma unroll
  for (int i = 0; i < 8; i++) {
    int row = m0 + ty * 8 + i;
    float ps = 0.f, pd = 0.f;
#pragma unroll
    for (int j = 0; j < 8; j++) { ps += acc[i][j] * asr[j]; pd += acc[i][j] * adr[j]; }
#pragma unroll
    for (int o = 4; o; o >>= 1) {
      ps += __shfl_down_sync(0xffffffffu, ps, o, 8);
      pd += __shfl_down_sync(0xffffffffu, pd, o, 8);
    }
    if (row < NN) {
      if ((tx & 7) == 0) {
        ((float*)&g_ssrc1[p][row])[tx >> 3] = ps;
        ((float*)&g_sdst1[p][row])[tx >> 3] = pd;
      }
      uint4 u;
      ((__half2*)&u)[0] = __floats2half2_rn(acc[i][0], acc[i][1]);
      ((__half2*)&u)[1] = __floats2half2_rn(acc[i][2], acc[i][3]);
      ((__half2*)&u)[2] = __floats2half2_rn(acc[i][4], acc[i][5]);
      ((__half2*)&u)[3] = __floats2half2_rn(acc[i][6], acc[i][7]);
      ((uint4*)(g_h1[p] + (size_t)row * HC))[tx] = u;
    }
  }
}

// ---------------- GAT1: single-pass softmax-aggregate, warp per dst node ----------------
__global__ __launch_bounds__(256) void k_gat1(const float* __restrict__ b1, int p) {
  __shared__ int    sIdx[8][32];
  __shared__ float4 sE[8][32];
  int wslot = threadIdx.x >> 5;
  int gw = (blockIdx.x * blockDim.x + threadIdx.x) >> 5;
  if (gw >= NN) return;
  int lane = threadIdx.x & 31;
  int base = g_rowptr[gw];
  int deg = g_rowptr[gw + 1] - base;
  float4 sd = g_sdst1[p][gw];
  int head = lane >> 3;
  const __half* h1p = g_h1[p];
  float acc[8] = {0, 0, 0, 0, 0, 0, 0, 0};
  float s0 = 0, s1 = 0, s2 = 0, s3 = 0;

  for (int c0 = 0; c0 <= deg; c0 += 32) {
    int i = c0 + lane;
    float4 e4 = {0, 0, 0, 0};
    int s = gw;
    if (i <= deg) {
      s = (i < deg) ? g_col[base + i] : gw;
      float4 ss = g_ssrc1[p][s];
      e4.x = __expf(lrelu(ss.x + sd.x));
      e4.y = __expf(lrelu(ss.y + sd.y));
      e4.z = __expf(lrelu(ss.z + sd.z));
      e4.w = __expf(lrelu(ss.w + sd.w));
      s0 += e4.x; s1 += e4.y; s2 += e4.z; s3 += e4.w;
    }
    sIdx[wslot][lane] = s;
    sE[wslot][lane] = e4;
    __syncwarp();
    int cnt = min(32, deg + 1 - c0);
#pragma unroll 8
    for (int j = 0; j < cnt; j++) {
      int sj = sIdx[wslot][j];
      float w = ((const float*)&sE[wslot][j])[head];
      uint4 raw = ((const uint4*)(h1p + (size_t)sj * HC))[lane];
      const __half2* ph = (const __half2*)&raw;
      float2 f0 = __half22float2(ph[0]);
      float2 f1 = __half22float2(ph[1]);
      float2 f2 = __half22float2(ph[2]);
      float2 f3 = __half22float2(ph[3]);
      acc[0] += w * f0.x; acc[1] += w * f0.y;
      acc[2] += w * f1.x; acc[3] += w * f1.y;
      acc[4] += w * f2.x; acc[5] += w * f2.y;
      acc[6] += w * f3.x; acc[7] += w * f3.y;
    }
    __syncwarp();
  }
  s0 = warpSum(s0); s1 = warpSum(s1); s2 = warpSum(s2); s3 = warpSum(s3);
  float sums[4] = {s0, s1, s2, s3};
  float inv = 1.f / sums[head];
  float4 bb0 = *(const float4*)(b1 + lane * 8);
  float4 bb1 = *(const float4*)(b1 + lane * 8 + 4);
  float bbs[8] = {bb0.x, bb0.y, bb0.z, bb0.w, bb1.x, bb1.y, bb1.z, bb1.w};
  uint4 u;
  float o[8];
#pragma unroll
  for (int j = 0; j < 8; j++) o[j] = fmaxf(acc[j] * inv + bbs[j], 0.f);
  ((__half2*)&u)[0] = __floats2half2_rn(o[0], o[1]);
  ((__half2*)&u)[1] = __floats2half2_rn(o[2], o[3]);
  ((__half2*)&u)[2] = __floats2half2_rn(o[4], o[5]);
  ((__half2*)&u)[3] = __floats2half2_rn(o[6], o[7]);
  ((uint4*)(g_out1[p] + (size_t)gw * HC))[lane] = u;
}

// ---------------- GEMM2: h2 = out1(fp16) @ W2 ; fused GAT2 scores ----------------
__global__ __launch_bounds__(256) void k_gemm2(const float* __restrict__ W2,
                                               const float* __restrict__ as2,
                                               const float* __restrict__ ad2, int p) {
  __shared__ float As[64][33];
  __shared__ float Bs[32][64];
  int tid = threadIdx.x;
  int tx = tid & 15, ty = tid >> 4;
  int m0 = blockIdx.x * 64;
  float acc[4][4] = {};
  const __half* o1p = g_out1[p];
  for (int k0 = 0; k0 < HC; k0 += 32) {
    for (int i = tid; i < 64 * 16; i += 256) {
      int r = i >> 4, c2 = i & 15;
      int row = m0 + r;
      float2 v = {0.f, 0.f};
      if (row < NN) v = __half22float2(((const __half2*)(o1p + (size_t)row * HC + k0))[c2]);
      As[r][c2 * 2] = v.x;
      As[r][c2 * 2 + 1] = v.y;
    }
    for (int i = tid; i < 32 * 64; i += 256) {
      int r = i >> 6, c = i & 63;
      Bs[r][c] = W2[(k0 + r) * 64 + c];
    }
    __syncthreads();
#pragma unroll
    for (int k = 0; k < 32; k++) {
      float a[4], b[4];
#pragma unroll
      for (int i = 0; i < 4; i++) a[i] = As[ty * 4 + i][k];
#pragma unroll
      for (int j = 0; j < 4; j++) b[j] = Bs[k][tx * 4 + j];
#pragma unroll
      for (int i = 0; i < 4; i++)
#pragma unroll
        for (int j = 0; j < 4; j++) acc[i][j] += a[i] * b[j];
    }
    __syncthreads();
  }
  float asr[4], adr[4];
#pragma unroll
  for (int j = 0; j < 4; j++) { asr[j] = __ldg(as2 + tx * 4 + j); adr[j] = __ldg(ad2 + tx * 4 + j); }
#pragma unroll
  for (int i = 0; i < 4; i++) {
    int row = m0 + ty * 4 + i;
    float ps = 0.f, pd = 0.f;
#pragma unroll
    for (int j = 0; j < 4; j++) { ps += acc[i][j] * asr[j]; pd += acc[i][j] * adr[j]; }
#pragma unroll
    for (int o = 8; o; o >>= 1) {
      ps += __shfl_down_sync(0xffffffffu, ps, o, 16);
      pd += __shfl_down_sync(0xffffffffu, pd, o, 16);
    }
    if (row < NN) {
      if (tx == 0) { g_ssrc2[p][row] = ps; g_sdst2[p][row] = pd; }
      uint2 u;
      ((__half2*)&u)[0] = __floats2half2_rn(acc[i][0], acc[i][1]);
      ((__half2*)&u)[1] = __floats2half2_rn(acc[i][2], acc[i][3]);
      ((uint2*)(g_h2[p] + (size_t)row * 64))[tx] = u;
    }
  }
}

// ---------------- GAT2: single-pass aggregate + mean-pool scatter ----------------
__global__ __launch_bounds__(256) void k_gat2(const float* __restrict__ b2,
                                              const int* __restrict__ batch, int t, int p) {
  __shared__ int   sIdx[8][32];
  __shared__ float sEs[8][32];
  int wslot = threadIdx.x >> 5;
  int gw = (blockIdx.x * blockDim.x + threadIdx.x) >> 5;
  if (gw >= NN) return;
  int lane = threadIdx.x & 31;
  int base = g_rowptr[gw];
  int deg = g_rowptr[gw + 1] - base;
  float sd = g_sdst2[p][gw];
  const __half* h2p = g_h2[p];
  const float* ss2 = g_ssrc2[p];
  float2 acc = {0, 0};
  float sum = 0.f;

  for (int c0 = 0; c0 <= deg; c0 += 32) {
    int i = c0 + lane;
    float e = 0.f;
    int s = gw;
    if (i <= deg) {
      s = (i < deg) ? g_col[base + i] : gw;
      e = __expf(lrelu(ss2[s] + sd));
      sum += e;
    }
    sIdx[wslot][lane] = s;
    sEs[wslot][lane] = e;
    __syncwarp();
    int cnt = min(32, deg + 1 - c0);
#pragma unroll 8
    for (int j = 0; j < cnt; j++) {
      int sj = sIdx[wslot][j];
      float ej = sEs[wslot][j];
      float2 v = __half22float2(((const __half2*)(h2p + (size_t)sj * 64))[lane]);
      acc.x += ej * v.x;
      acc.y += ej * v.y;
    }
    __syncwarp();
  }
  sum = warpSum(sum);
  float inv = 1.f / sum;
  int b = batch[gw];
  float v0 = acc.x * inv + b2[lane * 2];
  float v1 = acc.y * inv + b2[lane * 2 + 1];
  atomicAdd(&g_pooled[b * (SS * DD) + t * DD + lane * 2], v0);
  atomicAdd(&g_pooled[b * (SS * DD) + t * DD + lane * 2 + 1], v1);
}

// ---------------- final A: mean-pool normalize + qkv projection (96 blocks) ----------------
__global__ __launch_bounds__(192) void k_final_a(const float* __restrict__ ipw,
                                                 const float* __restrict__ ipb) {
  __shared__ float xr[64];
  int r = blockIdx.x;
  int tid = threadIdx.x;
  if (tid < 64) {
    int c = g_batchcnt[r / 6];
    float inv = 1.f / (c > 0 ? (float)c : 1.f);
    float v = g_pooled[r * 64 + tid] * inv;
    xr[tid] = v;
    g_sx[r * 64 + tid] = v;
  }
  __syncthreads();
  float acc = ipb[tid];
  const float* wr = &ipw[tid * 64];
#pragma unroll 8
  for (int c = 0; c < 64; c++) acc += xr[c] * wr[c];
  g_qkv[r * 192 + tid] = acc;
}

// ---------------- final B: attention + out_proj + LN + temporal mean + proj (16 blocks) ----------------
__global__ __launch_bounds__(128) void k_final_b(const float* __restrict__ opw, const float* __restrict__ opb,
                                                 const float* __restrict__ lng, const float* __restrict__ lnb,
                                                 const float* __restrict__ pw,  const float* __restrict__ pb,
                                                 float* __restrict__ out) {
  __shared__ float q[6 * 192];
  __shared__ float att[6 * 64];
  __shared__ float ym[6 * 64];
  __shared__ float zacc[64];
  int b = blockIdx.x;
  int tid = threadIdx.x;
  for (int i = tid; i < 6 * 192; i += 128) q[i] = g_qkv[b * 6 * 192 + i];
  if (tid < 64) zacc[tid] = 0.f;
  __syncthreads();
  if (tid < 24) {
    int s1 = tid >> 2, h = tid & 3;
    float sc[6];
    float mx = -1e30f;
    const float* qr = &q[s1 * 192 + h * 16];
    for (int s2 = 0; s2 < 6; s2++) {
      const float* kr = &q[s2 * 192 + 64 + h * 16];
      float d = 0.f;
#pragma unroll
      for (int u = 0; u < 16; u++) d += qr[u] * kr[u];
      sc[s2] = d * 0.25f;
      mx = fmaxf(mx, sc[s2]);
    }
    float ssum = 0.f;
    for (int s2 = 0; s2 < 6; s2++) { sc[s2] = __expf(sc[s2] - mx); ssum += sc[s2]; }
    float invs = 1.f / ssum;
    float o[16];
#pragma unroll
    for (int u = 0; u < 16; u++) o[u] = 0.f;
    for (int s2 = 0; s2 < 6; s2++) {
      float w = sc[s2] * invs;
      const float* vr = &q[s2 * 192 + 128 + h * 16];
#pragma unroll
      for (int u = 0; u < 16; u++) o[u] += w * vr[u];
    }
    for (int u = 0; u < 16; u++) att[s1 * 64 + h * 16 + u] = o[u];
  }
  __syncthreads();
  for (int i = tid; i < 6 * 64; i += 128) {
    int r = i >> 6, c = i & 63;
    float acc = opb[c];
    const float* ar = &att[r * 64];
    const float* wr = &opw[c * 64];
#pragma unroll 8
    for (int k = 0; k < 64; k++) acc += ar[k] * wr[k];
    ym[i] = acc + g_sx[(b * 6 + r) * 64 + c];
  }
  __syncthreads();
  int wid = tid >> 5, lane = tid & 31;
  for (int row = wid; row < 6; row += 4) {
    float y0 = ym[row * 64 + lane];
    float y1 = ym[row * 64 + 32 + lane];
    float s = warpSum(y0 + y1);
    float mu = s * (1.f / 64.f);
    float d0 = y0 - mu, d1 = y1 - mu;
    float vs = warpSum(d0 * d0 + d1 * d1);
    float var = vs * (1.f / 64.f);
    float r = rsqrtf(var + 1e-5f);
    float z0 = d0 * r * lng[lane] + lnb[lane];
    float z1 = d1 * r * lng[lane + 32] + lnb[lane + 32];
    atomicAdd(&zacc[lane], z0 * (1.f / 6.f));
    atomicAdd(&zacc[lane + 32], z1 * (1.f / 6.f));
  }
  __syncthreads();
  if (tid < 64) {
    float acc = pb[tid];
    const float* wr = &pw[tid * 64];
#pragma unroll 8
    for (int k = 0; k < 64; k++) acc += zacc[k] * wr[k];
    out[b * 64 + tid] = acc;
  }
}

// ---------------- launch ----------------
extern "C" void kernel_launch(void* const* d_in, const int* in_sizes, int n_in,
                              void* d_out, int out_size) {
  const float* x_seq = (const float*)d_in[0];
  const int*   ei    = (const int*)d_in[1];
  const int*   batch = (const int*)d_in[2];
  const float* W1    = (const float*)d_in[3];
  const float* as1   = (const float*)d_in[4];
  const float* ad1   = (const float*)d_in[5];
  const float* b1    = (const float*)d_in[6];
  const float* W2    = (const float*)d_in[7];
  const float* as2   = (const float*)d_in[8];
  const float* ad2   = (const float*)d_in[9];
  const float* b2    = (const float*)d_in[10];
  const float* ipw   = (const float*)d_in[11];
  const float* ipb   = (const float*)d_in[12];
  const float* opw   = (const float*)d_in[13];
  const float* opb   = (const float*)d_in[14];
  const float* lng   = (const float*)d_in[15];
  const float* lnb   = (const float*)d_in[16];
  const float* pw    = (const float*)d_in[17];
  const float* pb    = (const float*)d_in[18];
  float* out = (float*)d_out;

  // One-time handles (3 streams + 5 events, same as R6: measured zero allocator delta).
  static bool inited = false;
  static cudaStream_t st[NST];
  static cudaEvent_t ev_root, ev_csr;
  static cudaEvent_t ev_done[NST];
  if (!inited) {
    for (int i = 0; i < NST; i++) {
      cudaStreamCreateWithFlags(&st[i], cudaStreamNonBlocking);
      cudaEventCreateWithFlags(&ev_done[i], cudaEventDisableTiming);
    }
    cudaEventCreateWithFlags(&ev_root, cudaEventDisableTiming);
    cudaEventCreateWithFlags(&ev_csr, cudaEventDisableTiming);
    inited = true;
  }

  // Fork worker streams off the capture stream.
  cudaEventRecord(ev_root, 0);
  for (int i = 0; i < NST; i++) cudaStreamWaitEvent(st[i], ev_root, 0);

  // CSR build on the legacy stream; workers' gemm1s overlap it.
  k_init<<<(NN + 255) / 256, 256>>>();
  k_hist<<<(EE + 255) / 256, 256>>>(ei, batch);
  k_scan<<<1, 1024>>>();
  k_scatter<<<(EE + 255) / 256, 256>>>(ei);
  cudaEventRecord(ev_csr, 0);

  // Timestep -> carrier assignment: legacy carries t0; workers carry {t1,t4},{t2,t5},{t3}.
  // Legacy chain (same-stream ordering gives the CSR dependency for free):
  k_gemm1<<<(NN + 63) / 64, 256>>>(x_seq, W1, as1, ad1, 0);
  k_gat1<<<(NN * 32 + 255) / 256, 256>>>(b1, 0);
  k_gemm2<<<(NN + 63) / 64, 256>>>(W2, as2, ad2, 0);
  k_gat2<<<(NN * 32 + 255) / 256, 256>>>(b2, batch, 0, 0);

  // Worker chains: gemm1s first (independent of CSR), then wait ev_csr, then gats.
  const int wts[NST][2] = {{1, 4}, {2, 5}, {3, -1}};
  for (int i = 0; i < NST; i++) {
    cudaStream_t s = st[i];
    for (int j = 0; j < 2; j++) {
      int t = wts[i][j];
      if (t < 0) continue;
      k_gemm1<<<(NN + 63) / 64, 256, 0, s>>>(x_seq + (size_t)t * NN * FF, W1, as1, ad1, t);
    }
    cudaStreamWaitEvent(s, ev_csr, 0);
    for (int j = 0; j < 2; j++) {
      int t = wts[i][j];
      if (t < 0) continue;
      k_gat1<<<(NN * 32 + 255) / 256, 256, 0, s>>>(b1, t);
      k_gemm2<<<(NN + 63) / 64, 256, 0, s>>>(W2, as2, ad2, t);
      k_gat2<<<(NN * 32 + 255) / 256, 256, 0, s>>>(b2, batch, t, t);
    }
  }
  for (int i = 0; i < NST; i++) {
    cudaEventRecord(ev_done[i], st[i]);
    cudaStreamWaitEvent(0, ev_done[i], 0);
  }

  k_final_a<<<96, 192>>>(ipw, ipb);
  k_final_b<<<16, 128>>>(opw, opb, lng, lnb, pw, pb, out);
}